// round 3
// baseline (speedup 1.0000x reference)
#include <cuda_runtime.h>

// Fisher-Kolmogorov explicit Euler rollout, 2 micro-steps fused per kernel
// via shared-memory z-marching. Batch b active for pairs p < 5*dt_days[b];
// finishing pair (p == 5*dt-1) writes clipped output directly to d_out.

#define W        128
#define BATCH    2
#define SUBSTEPS 10
#define MAX_DAYS 4
#define NPAIRS   (SUBSTEPS * MAX_DAYS / 2)   // 20
#define PPD      (SUBSTEPS / 2)              // pairs per day = 5
#define MICRO_DT 0.1f

#define TY  8      // output y-rows per block
#define LZ  16     // output z-planes per block

#define VOL ((size_t)W * W * W)

// smem layout (floats):
//  uin : 5 planes x 12 rows x 128   -> [0, 7680)
//  umid: 3 planes x 10 rows x 128   -> [7680, 11520)
//  Dpl : 2 planes x 10 rows x 128   -> [11520, 14080)
//  Rpl : 2 planes x 10 rows x 128   -> [14080, 16640)
#define SM_UIN   0
#define SM_UMID  7680
#define SM_DPL   11520
#define SM_RPL   14080
#define SMEM_FLOATS 16640
#define SMEM_BYTES  (SMEM_FLOATS * 4)   // 66560

__device__ float g_buf0[BATCH * VOL];
__device__ float g_buf1[BATCH * VOL];

__device__ __forceinline__ float4 f4ld(const float* p) {
    return *reinterpret_cast<const float4*>(p);
}
__device__ __forceinline__ void f4st(float* p, float4 v) {
    *reinterpret_cast<float4*>(p) = v;
}

__device__ __forceinline__ float4 fk_update(float4 c, float4 ym, float4 yp,
                                            float4 zm, float4 zp,
                                            float lf, float rt,
                                            float4 Dv, float4 Rv)
{
    float4 o;
    float lx = lf  + c.y + ym.x + yp.x + zm.x + zp.x - 6.0f * c.x;
    float ly = c.x + c.z + ym.y + yp.y + zm.y + zp.y - 6.0f * c.y;
    float lz = c.y + c.w + ym.z + yp.z + zm.z + zp.z - 6.0f * c.z;
    float lw = c.z + rt  + ym.w + yp.w + zm.w + zp.w - 6.0f * c.w;
    o.x = c.x + MICRO_DT * (Dv.x * lx + Rv.x * c.x * (1.0f - c.x));
    o.y = c.y + MICRO_DT * (Dv.y * ly + Rv.y * c.y * (1.0f - c.y));
    o.z = c.z + MICRO_DT * (Dv.z * lz + Rv.z * c.z * (1.0f - c.z));
    o.w = c.w + MICRO_DT * (Dv.w * lw + Rv.w * c.w * (1.0f - c.w));
    return o;
}

__global__ __launch_bounds__(320)
void fk_pair(const float* __restrict__ usrc,
             float* __restrict__ udst,
             float* __restrict__ uout,
             const float* __restrict__ Dm,
             const float* __restrict__ rm,
             const int* __restrict__ dt_days,
             int pair)
{
    const int b  = blockIdx.z;
    const int dt = __ldg(dt_days + b);
    if (pair >= PPD * dt) return;                 // block-uniform early exit
    const bool fin = (pair == PPD * dt - 1);

    const int y0 = blockIdx.y * TY;
    const int z0 = blockIdx.x * LZ;
    const int tx = threadIdx.x;                   // 0..31 (float4 lane)
    const int ty = threadIdx.y;                   // 0..9
    const int tid = ty * 32 + tx;
    const size_t bb = (size_t)b * VOL;

    extern __shared__ float sm[];

    // ---- loaders ----
    auto load_uin = [&](int z) {
        const int s = (z + 10) % 5;
        #pragma unroll
        for (int idx = tid; idx < 12 * 32; idx += 320) {
            const int r = idx >> 5, ln = idx & 31;
            const int gy = y0 - 2 + r;
            float4 v = make_float4(0.f, 0.f, 0.f, 0.f);
            if ((unsigned)z < W && (unsigned)gy < W)
                v = f4ld(usrc + bb + ((size_t)z * W + gy) * W + ln * 4);
            f4st(sm + SM_UIN + s * 1536 + r * 128 + ln * 4, v);
        }
    };
    auto load_dr = [&](int z) {
        const int s  = (z + 2) & 1;
        const int gy = y0 - 1 + ty;               // ty in [0,10)
        float4 dv = make_float4(0.f, 0.f, 0.f, 0.f);
        float4 rv = make_float4(0.f, 0.f, 0.f, 0.f);
        if ((unsigned)z < W && (unsigned)gy < W) {
            const size_t g = bb + ((size_t)z * W + gy) * W + tx * 4;
            dv = f4ld(Dm + g);
            rv = f4ld(rm + g);
        }
        f4st(sm + SM_DPL + s * 1280 + ty * 128 + tx * 4, dv);
        f4st(sm + SM_RPL + s * 1280 + ty * 128 + tx * 4, rv);
    };

    // ---- step 1: mid(z) from uin rings; one row (ty) per thread ----
    auto compute_mid = [&](int z) {
        const int gy = y0 - 1 + ty;
        float4 o = make_float4(0.f, 0.f, 0.f, 0.f);
        if ((unsigned)z < W && (unsigned)gy < W) {
            const int s   = (z + 10) % 5;
            const int sm1 = (z + 9)  % 5;
            const int sp1 = (z + 11) % 5;
            const float* base = sm + SM_UIN + s * 1536 + (ty + 1) * 128;
            float4 c   = f4ld(base + tx * 4);
            float4 ymv = f4ld(sm + SM_UIN + s   * 1536 + ty       * 128 + tx * 4);
            float4 ypv = f4ld(sm + SM_UIN + s   * 1536 + (ty + 2) * 128 + tx * 4);
            float4 zmv = f4ld(sm + SM_UIN + sm1 * 1536 + (ty + 1) * 128 + tx * 4);
            float4 zpv = f4ld(sm + SM_UIN + sp1 * 1536 + (ty + 1) * 128 + tx * 4);
            float lf = (tx == 0)  ? 0.f : base[tx * 4 - 1];
            float rt = (tx == 31) ? 0.f : base[tx * 4 + 4];
            const int ds = (z + 2) & 1;
            float4 Dv = f4ld(sm + SM_DPL + ds * 1280 + ty * 128 + tx * 4);
            float4 Rv = f4ld(sm + SM_RPL + ds * 1280 + ty * 128 + tx * 4);
            o = fk_update(c, ymv, ypv, zmv, zpv, lf, rt, Dv, Rv);
        }
        f4st(sm + SM_UMID + ((z + 3) % 3) * 1280 + ty * 128 + tx * 4, o);
    };

    // ---- step 2: out(zo) from umid rings; rows ty<8 ----
    auto compute_out = [&](int zo) {
        if (ty >= TY) return;
        const int gy = y0 + ty;
        const int s   = zo % 3;
        const int sm1 = (zo + 2) % 3;
        const int sp1 = (zo + 1) % 3;
        const float* base = sm + SM_UMID + s * 1280 + (ty + 1) * 128;
        float4 c   = f4ld(base + tx * 4);
        float4 ymv = f4ld(sm + SM_UMID + s   * 1280 + ty       * 128 + tx * 4);
        float4 ypv = f4ld(sm + SM_UMID + s   * 1280 + (ty + 2) * 128 + tx * 4);
        float4 zmv = f4ld(sm + SM_UMID + sm1 * 1280 + (ty + 1) * 128 + tx * 4);
        float4 zpv = f4ld(sm + SM_UMID + sp1 * 1280 + (ty + 1) * 128 + tx * 4);
        float lf = (tx == 0)  ? 0.f : base[tx * 4 - 1];
        float rt = (tx == 31) ? 0.f : base[tx * 4 + 4];
        const int ds = zo & 1;
        float4 Dv = f4ld(sm + SM_DPL + ds * 1280 + (ty + 1) * 128 + tx * 4);
        float4 Rv = f4ld(sm + SM_RPL + ds * 1280 + (ty + 1) * 128 + tx * 4);
        float4 o = fk_update(c, ymv, ypv, zmv, zpv, lf, rt, Dv, Rv);

        const size_t g = bb + ((size_t)zo * W + gy) * W + tx * 4;
        if (fin) {
            o.x = fminf(fmaxf(o.x, 0.f), 1.f);
            o.y = fminf(fmaxf(o.y, 0.f), 1.f);
            o.z = fminf(fmaxf(o.z, 0.f), 1.f);
            o.w = fminf(fmaxf(o.w, 0.f), 1.f);
            f4st(uout + g, o);
        } else {
            f4st(udst + g, o);
        }
    };

    // ---- prologue: uin z0-2..z0+1, D/rho z0-1,z0; mid(z0-1), mid(z0) ----
    load_uin(z0 - 2); load_uin(z0 - 1); load_uin(z0); load_uin(z0 + 1);
    load_dr(z0 - 1);  load_dr(z0);
    __syncthreads();
    compute_mid(z0 - 1);
    compute_mid(z0);

    // ---- main march ----
    for (int zo = z0; zo < z0 + LZ; ++zo) {
        __syncthreads();                 // protect ring overwrites
        load_uin(zo + 2);
        load_dr(zo + 1);
        __syncthreads();
        compute_mid(zo + 1);
        __syncthreads();
        compute_out(zo);
    }
}

// Handles dt_days[b] == 0 batches: clipped copy of u_t0 into d_out.
__global__ __launch_bounds__(512)
void fk_tail(const float* __restrict__ u0,
             float* __restrict__ out,
             const int* __restrict__ dt_days)
{
    const int b = blockIdx.z >> 5;
    if (__ldg(dt_days + b) != 0) return;

    const int x4 = threadIdx.x << 2;
    const int y  = blockIdx.y * 4 + threadIdx.y;
    const int z  = (blockIdx.z & 31) * 4 + threadIdx.z;
    const size_t base = (((size_t)b * W + z) * W + y) * W + x4;

    float4 v = *reinterpret_cast<const float4*>(u0 + base);
    v.x = fminf(fmaxf(v.x, 0.0f), 1.0f);
    v.y = fminf(fmaxf(v.y, 0.0f), 1.0f);
    v.z = fminf(fmaxf(v.z, 0.0f), 1.0f);
    v.w = fminf(fmaxf(v.w, 0.0f), 1.0f);
    *reinterpret_cast<float4*>(out + base) = v;
}

extern "C" void kernel_launch(void* const* d_in, const int* in_sizes, int n_in,
                              void* d_out, int out_size)
{
    const float* u_t0    = (const float*)d_in[0];
    const float* D_map   = (const float*)d_in[1];
    const float* rho_map = (const float*)d_in[2];
    const int*   dt_days = (const int*)  d_in[3];
    float*       out     = (float*)d_out;

    cudaFuncSetAttribute(fk_pair, cudaFuncAttributeMaxDynamicSharedMemorySize,
                         SMEM_BYTES);

    float *p0 = nullptr, *p1 = nullptr;
    cudaGetSymbolAddress((void**)&p0, g_buf0);
    cudaGetSymbolAddress((void**)&p1, g_buf1);
    float* bufs[2] = { p0, p1 };

    dim3 block(32, 10, 1);
    dim3 grid(W / LZ, W / TY, BATCH);            // (8, 16, 2) = 256 blocks

    for (int p = 0; p < NPAIRS; ++p) {
        const float* src = (p == 0) ? u_t0 : bufs[(p + 1) & 1];
        float*       dst = bufs[p & 1];
        fk_pair<<<grid, block, SMEM_BYTES>>>(src, dst, out, D_map, rho_map,
                                             dt_days, p);
    }

    dim3 tblock(32, 4, 4);
    dim3 tgrid(1, W / 4, (W / 4) * BATCH);
    fk_tail<<<tgrid, tblock>>>(u_t0, out, dt_days);

    (void)in_sizes; (void)n_in; (void)out_size;
}

// round 4
// speedup vs baseline: 1.1486x; 1.1486x over previous
#include <cuda_runtime.h>

// Fisher-Kolmogorov rollout, 2 micro-steps fused per kernel via smem
// z-marching. Redesigned after R3: 512-thread blocks, minimal ring buffers
// (111KB smem -> 2 CTAs/SM), 2 syncs/plane instead of 3.

#define W        128
#define BATCH    2
#define SUBSTEPS 10
#define MAX_DAYS 4
#define NPAIRS   (SUBSTEPS * MAX_DAYS / 2)   // 20
#define PPD      (SUBSTEPS / 2)              // 5 pairs per day
#define MICRO_DT 0.1f

#define TY  16     // output y-rows per block
#define LZ  8      // output z-planes per block

#define VOL ((size_t)W * W * W)

// smem rings (floats):
//  UIN : 3 planes x 20 rows x 128  (y-halo 2)
//  MID : 3 planes x 18 rows x 128  (y-halo 1)
//  DPL : 3 planes x 18 rows x 128
//  RPL : 3 planes x 18 rows x 128
#define SM_UIN  0
#define SM_MID  7680
#define SM_DPL  (7680 + 6912)
#define SM_RPL  (7680 + 6912 + 6912)
#define SMEM_FLOATS (7680 + 3 * 6912)
#define SMEM_BYTES  (SMEM_FLOATS * 4)        // 113664 B

#define UIN_P 2560   // 20*128
#define MRW_P 2304   // 18*128

__device__ float g_buf0[BATCH * VOL];
__device__ float g_buf1[BATCH * VOL];

__device__ __forceinline__ float4 f4ld(const float* p) {
    return *reinterpret_cast<const float4*>(p);
}
__device__ __forceinline__ void f4st(float* p, float4 v) {
    *reinterpret_cast<float4*>(p) = v;
}

__device__ __forceinline__ float4 fk_update(float4 c, float4 ym, float4 yp,
                                            float4 zm, float4 zp,
                                            float lf, float rt,
                                            float4 Dv, float4 Rv)
{
    float4 o;
    float lx = lf  + c.y + ym.x + yp.x + zm.x + zp.x - 6.0f * c.x;
    float ly = c.x + c.z + ym.y + yp.y + zm.y + zp.y - 6.0f * c.y;
    float lz = c.y + c.w + ym.z + yp.z + zm.z + zp.z - 6.0f * c.z;
    float lw = c.z + rt  + ym.w + yp.w + zm.w + zp.w - 6.0f * c.w;
    o.x = c.x + MICRO_DT * (Dv.x * lx + Rv.x * c.x * (1.0f - c.x));
    o.y = c.y + MICRO_DT * (Dv.y * ly + Rv.y * c.y * (1.0f - c.y));
    o.z = c.z + MICRO_DT * (Dv.z * lz + Rv.z * c.z * (1.0f - c.z));
    o.w = c.w + MICRO_DT * (Dv.w * lw + Rv.w * c.w * (1.0f - c.w));
    return o;
}

__global__ __launch_bounds__(512, 2)
void fk_pair(const float* __restrict__ usrc,
             float* __restrict__ udst,
             float* __restrict__ uout,
             const float* __restrict__ Dm,
             const float* __restrict__ rm,
             const int* __restrict__ dt_days,
             int pair)
{
    const int b  = blockIdx.z;
    const int dt = __ldg(dt_days + b);
    if (pair >= PPD * dt) return;                 // block-uniform early exit
    const bool fin = (pair == PPD * dt - 1);

    const int y0 = blockIdx.y * TY;
    const int z0 = blockIdx.x * LZ;
    const int tx = threadIdx.x;                   // 0..31 (float4 lane)
    const int ty = threadIdx.y;                   // 0..15
    const int tid = ty * 32 + tx;
    const size_t bb = (size_t)b * VOL;

    extern __shared__ float sm[];

    // load u plane z into UIN ring slot (z+3)%3, rows y0-2..y0+17
    auto ld_uin = [&](int z) {
        float* dstp = sm + SM_UIN + ((z + 3) % 3) * UIN_P;
        #pragma unroll
        for (int idx = tid; idx < 20 * 32; idx += 512) {
            const int r = idx >> 5, ln = idx & 31;
            const int gy = y0 - 2 + r;
            float4 v = make_float4(0.f, 0.f, 0.f, 0.f);
            if ((unsigned)z < W && (unsigned)gy < W)
                v = f4ld(usrc + bb + ((size_t)z * W + gy) * W + ln * 4);
            f4st(dstp + r * 128 + ln * 4, v);
        }
    };

    // load D,rho plane z into slot (z+3)%3, rows y0-1..y0+16
    auto ld_dr = [&](int z) {
        const int s = (z + 3) % 3;
        float* dD = sm + SM_DPL + s * MRW_P;
        float* dR = sm + SM_RPL + s * MRW_P;
        #pragma unroll
        for (int idx = tid; idx < 18 * 32; idx += 512) {
            const int r = idx >> 5, ln = idx & 31;
            const int gy = y0 - 1 + r;
            float4 dv = make_float4(0.f, 0.f, 0.f, 0.f);
            float4 rv = make_float4(0.f, 0.f, 0.f, 0.f);
            if ((unsigned)z < W && (unsigned)gy < W) {
                const size_t g = bb + ((size_t)z * W + gy) * W + ln * 4;
                dv = f4ld(Dm + g);
                rv = f4ld(rm + g);
            }
            f4st(dD + r * 128 + ln * 4, dv);
            f4st(dR + r * 128 + ln * 4, rv);
        }
    };

    // mid(z) from UIN(z-1,z,z+1); rows y0-1..y0+16 -> MID slot (z+3)%3
    auto cmp_mid = [&](int z) {
        const float* pc = sm + SM_UIN + ((z + 3) % 3) * UIN_P;
        const float* pm = sm + SM_UIN + ((z + 2) % 3) * UIN_P;
        const float* pp = sm + SM_UIN + ((z + 4) % 3) * UIN_P;
        const float* pD = sm + SM_DPL + ((z + 3) % 3) * MRW_P;
        const float* pR = sm + SM_RPL + ((z + 3) % 3) * MRW_P;
        float* pO = sm + SM_MID + ((z + 3) % 3) * MRW_P;
        #pragma unroll
        for (int idx = tid; idx < 18 * 32; idx += 512) {
            const int r = idx >> 5, ln = idx & 31;
            const int gy = y0 - 1 + r;
            const int x4 = ln * 4;
            float4 o = make_float4(0.f, 0.f, 0.f, 0.f);
            if ((unsigned)z < W && (unsigned)gy < W) {
                const float* base = pc + (r + 1) * 128;
                float4 c   = f4ld(base + x4);
                float4 ymv = f4ld(pc + r * 128 + x4);
                float4 ypv = f4ld(pc + (r + 2) * 128 + x4);
                float4 zmv = f4ld(pm + (r + 1) * 128 + x4);
                float4 zpv = f4ld(pp + (r + 1) * 128 + x4);
                float lf = (x4 == 0)       ? 0.f : base[x4 - 1];
                float rt = (x4 == W - 4)   ? 0.f : base[x4 + 4];
                float4 Dv = f4ld(pD + r * 128 + x4);
                float4 Rv = f4ld(pR + r * 128 + x4);
                o = fk_update(c, ymv, ypv, zmv, zpv, lf, rt, Dv, Rv);
            }
            f4st(pO + r * 128 + x4, o);
        }
    };

    // out(z) from MID(z-1,z,z+1); one row per ty
    auto cmp_out = [&](int z) {
        const float* pc = sm + SM_MID + ((z + 3) % 3) * MRW_P;
        const float* pm = sm + SM_MID + ((z + 2) % 3) * MRW_P;
        const float* pp = sm + SM_MID + ((z + 4) % 3) * MRW_P;
        const float* pD = sm + SM_DPL + ((z + 3) % 3) * MRW_P;
        const float* pR = sm + SM_RPL + ((z + 3) % 3) * MRW_P;
        const int x4 = tx * 4;
        const int gy = y0 + ty;
        const float* base = pc + (ty + 1) * 128;
        float4 c   = f4ld(base + x4);
        float4 ymv = f4ld(pc + ty * 128 + x4);
        float4 ypv = f4ld(pc + (ty + 2) * 128 + x4);
        float4 zmv = f4ld(pm + (ty + 1) * 128 + x4);
        float4 zpv = f4ld(pp + (ty + 1) * 128 + x4);
        float lf = (x4 == 0)     ? 0.f : base[x4 - 1];
        float rt = (x4 == W - 4) ? 0.f : base[x4 + 4];
        float4 Dv = f4ld(pD + (ty + 1) * 128 + x4);
        float4 Rv = f4ld(pR + (ty + 1) * 128 + x4);
        float4 o = fk_update(c, ymv, ypv, zmv, zpv, lf, rt, Dv, Rv);

        const size_t g = bb + ((size_t)z * W + gy) * W + x4;
        if (fin) {
            o.x = fminf(fmaxf(o.x, 0.f), 1.f);
            o.y = fminf(fmaxf(o.y, 0.f), 1.f);
            o.z = fminf(fmaxf(o.z, 0.f), 1.f);
            o.w = fminf(fmaxf(o.w, 0.f), 1.f);
            f4st(uout + g, o);
        } else {
            f4st(udst + g, o);
        }
    };

    // ---- prologue ----
    ld_uin(z0 - 2); ld_uin(z0 - 1); ld_uin(z0); ld_dr(z0 - 1);
    __syncthreads();
    cmp_mid(z0 - 1);
    __syncthreads();
    ld_uin(z0 + 1); ld_dr(z0);      // overwrites uin slot of z0-2 (done)
    __syncthreads();
    cmp_mid(z0);
    __syncthreads();                // fences uin(z0-1) reads vs A(z0) write

    // ---- main march: A | S1 | B | S2 | C  (C -> next A is hazard-free) ----
    for (int z = z0; z < z0 + LZ; ++z) {
        ld_uin(z + 2); ld_dr(z + 1);     // A
        __syncthreads();                  // S1
        cmp_mid(z + 1);                   // B
        __syncthreads();                  // S2
        cmp_out(z);                       // C
    }
}

// Handles dt_days[b] == 0 batches: clipped copy of u_t0 into d_out.
__global__ __launch_bounds__(512)
void fk_tail(const float* __restrict__ u0,
             float* __restrict__ out,
             const int* __restrict__ dt_days)
{
    const int b = blockIdx.z >> 5;
    if (__ldg(dt_days + b) != 0) return;

    const int x4 = threadIdx.x << 2;
    const int y  = blockIdx.y * 4 + threadIdx.y;
    const int z  = (blockIdx.z & 31) * 4 + threadIdx.z;
    const size_t base = (((size_t)b * W + z) * W + y) * W + x4;

    float4 v = *reinterpret_cast<const float4*>(u0 + base);
    v.x = fminf(fmaxf(v.x, 0.0f), 1.0f);
    v.y = fminf(fmaxf(v.y, 0.0f), 1.0f);
    v.z = fminf(fmaxf(v.z, 0.0f), 1.0f);
    v.w = fminf(fmaxf(v.w, 0.0f), 1.0f);
    *reinterpret_cast<float4*>(out + base) = v;
}

extern "C" void kernel_launch(void* const* d_in, const int* in_sizes, int n_in,
                              void* d_out, int out_size)
{
    const float* u_t0    = (const float*)d_in[0];
    const float* D_map   = (const float*)d_in[1];
    const float* rho_map = (const float*)d_in[2];
    const int*   dt_days = (const int*)  d_in[3];
    float*       out     = (float*)d_out;

    cudaFuncSetAttribute(fk_pair, cudaFuncAttributeMaxDynamicSharedMemorySize,
                         SMEM_BYTES);

    float *p0 = nullptr, *p1 = nullptr;
    cudaGetSymbolAddress((void**)&p0, g_buf0);
    cudaGetSymbolAddress((void**)&p1, g_buf1);
    float* bufs[2] = { p0, p1 };

    dim3 block(32, TY, 1);                        // 512 threads
    dim3 grid(W / LZ, W / TY, BATCH);             // (16, 8, 2) = 256 blocks

    for (int p = 0; p < NPAIRS; ++p) {
        const float* src = (p == 0) ? u_t0 : bufs[(p + 1) & 1];
        float*       dst = bufs[p & 1];
        fk_pair<<<grid, block, SMEM_BYTES>>>(src, dst, out, D_map, rho_map,
                                             dt_days, p);
    }

    dim3 tblock(32, 4, 4);
    dim3 tgrid(1, W / 4, (W / 4) * BATCH);
    fk_tail<<<tgrid, tblock>>>(u_t0, out, dt_days);

    (void)in_sizes; (void)n_in; (void)out_size;
}

// round 5
// speedup vs baseline: 1.5241x; 1.3269x over previous
#include <cuda_runtime.h>
#include <cuda_fp16.h>

// Fisher-Kolmogorov rollout. R5: back to per-step kernels (no smem pipeline).
// Traffic cuts: (1) D,rho precomputed once into interleaved half2 {D,rho}
// (halves their read traffic, error ~1.5e-4 << 1e-3), (2) register z-marching
// (z-neighbors reused in registers), (3) 128x8x16 tiles + shfl x-halo.

#define W        128
#define BATCH    2
#define SUBSTEPS 10
#define MAX_DAYS 4
#define NSTEPS   (SUBSTEPS * MAX_DAYS)
#define MICRO_DT 0.1f

#define TY  8
#define LZ  16

#define VOL  ((size_t)W * W * W)
#define NTOT (BATCH * VOL)

__device__ float g_buf0[NTOT];
__device__ float g_buf1[NTOT];
__device__ __half2 g_dr[NTOT];          // {D, rho} per point, 16 MB

struct __align__(16) H24 { __half2 h[4]; };

__device__ __forceinline__ float4 f4ld(const float* p) {
    return *reinterpret_cast<const float4*>(p);
}

// Pack D,rho -> half2 (one-time; runs inside the graph, deterministic).
__global__ __launch_bounds__(256)
void prep_dr(const float* __restrict__ D, const float* __restrict__ R,
             __half2* __restrict__ dr)
{
    const size_t i = ((size_t)blockIdx.x * 256 + threadIdx.x) * 4;
    float4 d = f4ld(D + i);
    float4 r = f4ld(R + i);
    H24 q;
    q.h[0] = __floats2half2_rn(d.x, r.x);
    q.h[1] = __floats2half2_rn(d.y, r.y);
    q.h[2] = __floats2half2_rn(d.z, r.z);
    q.h[3] = __floats2half2_rn(d.w, r.w);
    *reinterpret_cast<H24*>(dr + i) = q;
}

__device__ __forceinline__ void fk_comp(float& o, float c, float nb5,
                                        float lap_c, __half2 drh)
{
    const float2 dr2 = __half22float2(drh);       // x=D, y=rho
    const float lap = nb5 + lap_c - 6.0f * c;
    o = c + MICRO_DT * (dr2.x * lap + dr2.y * c * (1.0f - c));
}

__global__ __launch_bounds__(256)
void fk_step(const float* __restrict__ usrc,
             float* __restrict__ udst,
             float* __restrict__ uout,
             const __half2* __restrict__ dr,
             const int* __restrict__ dt_days,
             int day, int sub)
{
    const int b  = blockIdx.z;
    const int dt = __ldg(dt_days + b);
    if (day >= dt) return;                              // block-uniform
    const bool fin = (day == dt - 1) && (sub == SUBSTEPS - 1);

    const int tx = threadIdx.x;                         // 0..31
    const int y  = blockIdx.y * TY + threadIdx.y;       // 0..127
    const int z0 = blockIdx.x * LZ;
    const int x4 = tx << 2;
    const size_t bb = (size_t)b * VOL;

    size_t base = bb + (((size_t)z0 * W) + y) * W + x4; // row (z0, y)
    const size_t PL = (size_t)W * W;

    const float4 zero4 = make_float4(0.f, 0.f, 0.f, 0.f);
    float4 cm = (z0 > 0) ? f4ld(usrc + base - PL) : zero4;
    float4 cc = f4ld(usrc + base);

    #pragma unroll 4
    for (int dz = 0; dz < LZ; ++dz) {
        const int z = z0 + dz;
        const float4 cp = (z < W - 1) ? f4ld(usrc + base + PL) : zero4;
        const float4 ym = (y > 0)     ? f4ld(usrc + base - W)  : zero4;
        const float4 yp = (y < W - 1) ? f4ld(usrc + base + W)  : zero4;

        float lf = __shfl_up_sync(0xffffffffu, cc.w, 1);
        float rt = __shfl_down_sync(0xffffffffu, cc.x, 1);
        if (tx == 0)  lf = 0.0f;
        if (tx == 31) rt = 0.0f;

        const H24 q = *reinterpret_cast<const H24*>(dr + base);

        float4 o;
        fk_comp(o.x, cc.x, lf   + cc.y, ym.x + yp.x + cm.x + cp.x, q.h[0]);
        fk_comp(o.y, cc.y, cc.x + cc.z, ym.y + yp.y + cm.y + cp.y, q.h[1]);
        fk_comp(o.z, cc.z, cc.y + cc.w, ym.z + yp.z + cm.z + cp.z, q.h[2]);
        fk_comp(o.w, cc.w, cc.z + rt,   ym.w + yp.w + cm.w + cp.w, q.h[3]);

        if (fin) {
            o.x = fminf(fmaxf(o.x, 0.f), 1.f);
            o.y = fminf(fmaxf(o.y, 0.f), 1.f);
            o.z = fminf(fmaxf(o.z, 0.f), 1.f);
            o.w = fminf(fmaxf(o.w, 0.f), 1.f);
            *reinterpret_cast<float4*>(uout + base) = o;
        } else {
            *reinterpret_cast<float4*>(udst + base) = o;
        }

        cm = cc; cc = cp;
        base += PL;
    }
}

// Handles dt_days[b] == 0 batches: clipped copy of u_t0 into d_out.
__global__ __launch_bounds__(512)
void fk_tail(const float* __restrict__ u0,
             float* __restrict__ out,
             const int* __restrict__ dt_days)
{
    const int b = blockIdx.z >> 5;
    if (__ldg(dt_days + b) != 0) return;

    const int x4 = threadIdx.x << 2;
    const int y  = blockIdx.y * 4 + threadIdx.y;
    const int z  = (blockIdx.z & 31) * 4 + threadIdx.z;
    const size_t base = (((size_t)b * W + z) * W + y) * W + x4;

    float4 v = f4ld(u0 + base);
    v.x = fminf(fmaxf(v.x, 0.0f), 1.0f);
    v.y = fminf(fmaxf(v.y, 0.0f), 1.0f);
    v.z = fminf(fmaxf(v.z, 0.0f), 1.0f);
    v.w = fminf(fmaxf(v.w, 0.0f), 1.0f);
    *reinterpret_cast<float4*>(out + base) = v;
}

extern "C" void kernel_launch(void* const* d_in, const int* in_sizes, int n_in,
                              void* d_out, int out_size)
{
    const float* u_t0    = (const float*)d_in[0];
    const float* D_map   = (const float*)d_in[1];
    const float* rho_map = (const float*)d_in[2];
    const int*   dt_days = (const int*)  d_in[3];
    float*       out     = (float*)d_out;

    float *p0 = nullptr, *p1 = nullptr;
    __half2* dr = nullptr;
    cudaGetSymbolAddress((void**)&p0, g_buf0);
    cudaGetSymbolAddress((void**)&p1, g_buf1);
    cudaGetSymbolAddress((void**)&dr, g_dr);
    float* bufs[2] = { p0, p1 };

    // One-time D/rho packing (inside the graph; deterministic).
    prep_dr<<<(unsigned)(NTOT / 4 / 256), 256>>>(D_map, rho_map, dr);

    dim3 block(32, TY, 1);                       // 256 threads
    dim3 grid(W / LZ, W / TY, BATCH);            // (8, 16, 2) = 256 blocks

    for (int s = 0; s < NSTEPS; ++s) {
        const float* src = (s == 0) ? u_t0 : bufs[s & 1];
        float*       dst = bufs[(s + 1) & 1];
        fk_step<<<grid, block>>>(src, dst, out, dr, dt_days,
                                 s / SUBSTEPS, s % SUBSTEPS);
    }

    dim3 tblock(32, 4, 4);
    dim3 tgrid(1, W / 4, (W / 4) * BATCH);
    fk_tail<<<tgrid, tblock>>>(u_t0, out, dt_days);

    (void)in_sizes; (void)n_in; (void)out_size;
}

// round 6
// speedup vs baseline: 2.1225x; 1.3926x over previous
#include <cuda_runtime.h>
#include <cuda_fp16.h>

// Fisher-Kolmogorov rollout. R6 = R5 body (fp16 {D,rho} packed, register
// z-marching, shfl x-halo) with LZ cut 16->4: 1024 blocks / 262K threads
// restores the parallelism R5 lacked (occ 12.6% -> ~50%).

#define W        128
#define BATCH    2
#define SUBSTEPS 10
#define MAX_DAYS 4
#define NSTEPS   (SUBSTEPS * MAX_DAYS)
#define MICRO_DT 0.1f

#define TY  8
#define LZ  4

#define VOL  ((size_t)W * W * W)
#define NTOT (BATCH * VOL)

__device__ float g_buf0[NTOT];
__device__ float g_buf1[NTOT];
__device__ __half2 g_dr[NTOT];          // {D, rho} per point, 16 MB

struct __align__(16) H24 { __half2 h[4]; };

__device__ __forceinline__ float4 f4ld(const float* p) {
    return *reinterpret_cast<const float4*>(p);
}

// Pack D,rho -> half2 (one-time; runs inside the graph, deterministic).
__global__ __launch_bounds__(256)
void prep_dr(const float* __restrict__ D, const float* __restrict__ R,
             __half2* __restrict__ dr)
{
    const size_t i = ((size_t)blockIdx.x * 256 + threadIdx.x) * 4;
    float4 d = f4ld(D + i);
    float4 r = f4ld(R + i);
    H24 q;
    q.h[0] = __floats2half2_rn(d.x, r.x);
    q.h[1] = __floats2half2_rn(d.y, r.y);
    q.h[2] = __floats2half2_rn(d.z, r.z);
    q.h[3] = __floats2half2_rn(d.w, r.w);
    *reinterpret_cast<H24*>(dr + i) = q;
}

__device__ __forceinline__ void fk_comp(float& o, float c, float nb5,
                                        float lap_c, __half2 drh)
{
    const float2 dr2 = __half22float2(drh);       // x=D, y=rho
    const float lap = nb5 + lap_c - 6.0f * c;
    o = c + MICRO_DT * (dr2.x * lap + dr2.y * c * (1.0f - c));
}

__global__ __launch_bounds__(256)
void fk_step(const float* __restrict__ usrc,
             float* __restrict__ udst,
             float* __restrict__ uout,
             const __half2* __restrict__ dr,
             const int* __restrict__ dt_days,
             int day, int sub)
{
    const int b  = blockIdx.z;
    const int dt = __ldg(dt_days + b);
    if (day >= dt) return;                              // block-uniform
    const bool fin = (day == dt - 1) && (sub == SUBSTEPS - 1);

    const int tx = threadIdx.x;                         // 0..31
    const int y  = blockIdx.y * TY + threadIdx.y;       // 0..127
    const int z0 = blockIdx.x * LZ;
    const int x4 = tx << 2;
    const size_t bb = (size_t)b * VOL;

    size_t base = bb + (((size_t)z0 * W) + y) * W + x4; // row (z0, y)
    const size_t PL = (size_t)W * W;

    const float4 zero4 = make_float4(0.f, 0.f, 0.f, 0.f);
    float4 cm = (z0 > 0) ? f4ld(usrc + base - PL) : zero4;
    float4 cc = f4ld(usrc + base);

    #pragma unroll
    for (int dz = 0; dz < LZ; ++dz) {
        const int z = z0 + dz;
        // Independent loads issued back-to-back: MLP = 4 per iteration.
        const float4 cp = (z < W - 1) ? f4ld(usrc + base + PL) : zero4;
        const float4 ym = (y > 0)     ? f4ld(usrc + base - W)  : zero4;
        const float4 yp = (y < W - 1) ? f4ld(usrc + base + W)  : zero4;
        const H24 q = *reinterpret_cast<const H24*>(dr + base);

        float lf = __shfl_up_sync(0xffffffffu, cc.w, 1);
        float rt = __shfl_down_sync(0xffffffffu, cc.x, 1);
        if (tx == 0)  lf = 0.0f;
        if (tx == 31) rt = 0.0f;

        float4 o;
        fk_comp(o.x, cc.x, lf   + cc.y, ym.x + yp.x + cm.x + cp.x, q.h[0]);
        fk_comp(o.y, cc.y, cc.x + cc.z, ym.y + yp.y + cm.y + cp.y, q.h[1]);
        fk_comp(o.z, cc.z, cc.y + cc.w, ym.z + yp.z + cm.z + cp.z, q.h[2]);
        fk_comp(o.w, cc.w, cc.z + rt,   ym.w + yp.w + cm.w + cp.w, q.h[3]);

        if (fin) {
            o.x = fminf(fmaxf(o.x, 0.f), 1.f);
            o.y = fminf(fmaxf(o.y, 0.f), 1.f);
            o.z = fminf(fmaxf(o.z, 0.f), 1.f);
            o.w = fminf(fmaxf(o.w, 0.f), 1.f);
            *reinterpret_cast<float4*>(uout + base) = o;
        } else {
            *reinterpret_cast<float4*>(udst + base) = o;
        }

        cm = cc; cc = cp;
        base += PL;
    }
}

// Handles dt_days[b] == 0 batches: clipped copy of u_t0 into d_out.
__global__ __launch_bounds__(512)
void fk_tail(const float* __restrict__ u0,
             float* __restrict__ out,
             const int* __restrict__ dt_days)
{
    const int b = blockIdx.z >> 5;
    if (__ldg(dt_days + b) != 0) return;

    const int x4 = threadIdx.x << 2;
    const int y  = blockIdx.y * 4 + threadIdx.y;
    const int z  = (blockIdx.z & 31) * 4 + threadIdx.z;
    const size_t base = (((size_t)b * W + z) * W + y) * W + x4;

    float4 v = f4ld(u0 + base);
    v.x = fminf(fmaxf(v.x, 0.0f), 1.0f);
    v.y = fminf(fmaxf(v.y, 0.0f), 1.0f);
    v.z = fminf(fmaxf(v.z, 0.0f), 1.0f);
    v.w = fminf(fmaxf(v.w, 0.0f), 1.0f);
    *reinterpret_cast<float4*>(out + base) = v;
}

extern "C" void kernel_launch(void* const* d_in, const int* in_sizes, int n_in,
                              void* d_out, int out_size)
{
    const float* u_t0    = (const float*)d_in[0];
    const float* D_map   = (const float*)d_in[1];
    const float* rho_map = (const float*)d_in[2];
    const int*   dt_days = (const int*)  d_in[3];
    float*       out     = (float*)d_out;

    float *p0 = nullptr, *p1 = nullptr;
    __half2* dr = nullptr;
    cudaGetSymbolAddress((void**)&p0, g_buf0);
    cudaGetSymbolAddress((void**)&p1, g_buf1);
    cudaGetSymbolAddress((void**)&dr, g_dr);
    float* bufs[2] = { p0, p1 };

    // One-time D/rho packing (inside the graph; deterministic).
    prep_dr<<<(unsigned)(NTOT / 4 / 256), 256>>>(D_map, rho_map, dr);

    dim3 block(32, TY, 1);                       // 256 threads
    dim3 grid(W / LZ, W / TY, BATCH);            // (32, 16, 2) = 1024 blocks

    for (int s = 0; s < NSTEPS; ++s) {
        const float* src = (s == 0) ? u_t0 : bufs[s & 1];
        float*       dst = bufs[(s + 1) & 1];
        fk_step<<<grid, block>>>(src, dst, out, dr, dt_days,
                                 s / SUBSTEPS, s % SUBSTEPS);
    }

    dim3 tblock(32, 4, 4);
    dim3 tgrid(1, W / 4, (W / 4) * BATCH);
    fk_tail<<<tgrid, tblock>>>(u_t0, out, dt_days);

    (void)in_sizes; (void)n_in; (void)out_size;
}